// round 12
// baseline (speedup 1.0000x reference)
#include <cuda_runtime.h>
#include <math.h>

#define BATCH 4096
#define FEAT  4096
#define WARPS_PER_BLOCK 9
#define THREADS (WARPS_PER_BLOCK * 32)          // 288
#define GRID ((BATCH + WARPS_PER_BLOCK - 1) / WARPS_PER_BLOCK)  // 456: all resident, 1 wave

__global__ __launch_bounds__(THREADS, 4)        // cap regs so 3-4 CTAs/SM fit
void fused_loss_kernel(const float* __restrict__ o1,
                       const float* __restrict__ o2,
                       const float* __restrict__ o3,
                       float* __restrict__ out) {
    const int tid  = threadIdx.x;
    const int lane = tid & 31;
    const int wid  = tid >> 5;

    __shared__ float s_block_sum;
    if (tid == 0) s_block_sum = 0.0f;
    __syncthreads();

    const int row = blockIdx.x * WARPS_PER_BLOCK + wid;
    if (row < BATCH) {
        const size_t base = (size_t)row * FEAT;
        const float4* __restrict__ a = reinterpret_cast<const float4*>(o1 + base);
        const float4* __restrict__ b = reinterpret_cast<const float4*>(o2 + base);
        const float4* __restrict__ c = reinterpret_cast<const float4*>(o3 + base);

        float s13 = 0.0f;
        float s12 = 0.0f;

        // 1024 float4 per row / 32 lanes = 32 iterations; unroll 2 -> 6 loads
        // in flight per lane, no block barriers anywhere in the hot path.
#pragma unroll 2
        for (int it = 0; it < (FEAT / 4) / 32; ++it) {
            int i = lane + it * 32;
            float4 x = a[i];
            float4 y = b[i];
            float4 z = c[i];

            float d;
            d = x.x - z.x; s13 = fmaf(d, d, s13);
            d = x.y - z.y; s13 = fmaf(d, d, s13);
            d = x.z - z.z; s13 = fmaf(d, d, s13);
            d = x.w - z.w; s13 = fmaf(d, d, s13);

            d = x.x - y.x; s12 = fmaf(d, d, s12);
            d = x.y - y.y; s12 = fmaf(d, d, s12);
            d = x.z - y.z; s12 = fmaf(d, d, s12);
            d = x.w - y.w; s12 = fmaf(d, d, s12);
        }

        // Warp-local reduction only.
#pragma unroll
        for (int off = 16; off > 0; off >>= 1) {
            s13 += __shfl_down_sync(0xFFFFFFFFu, s13, off);
            s12 += __shfl_down_sync(0xFFFFFFFFu, s12, off);
        }

        if (lane == 0) {
            float compare = 2.0f - sqrtf(s13) + sqrtf(s12);
            atomicAdd(&s_block_sum, fmaxf(0.0f, compare));  // smem atomic, 9/block
        }
    }
    __syncthreads();

    if (tid == 0) {
        // Broadcast-sum over [B,B] == B * sum_b(hinged). One overlapped ATOMG
        // per block; out[] zeroed by cudaMemsetAsync in kernel_launch.
        atomicAdd(out, s_block_sum * (float)BATCH);
    }
}

extern "C" void kernel_launch(void* const* d_in, const int* in_sizes, int n_in,
                              void* d_out, int out_size) {
    const float* o1 = (const float*)d_in[0];
    const float* o2 = (const float*)d_in[1];
    const float* o3 = (const float*)d_in[2];
    float* out = (float*)d_out;

    cudaMemsetAsync(out, 0, sizeof(float));
    fused_loss_kernel<<<GRID, THREADS>>>(o1, o2, o3, out);
}

// round 13
// speedup vs baseline: 1.0412x; 1.0412x over previous
#include <cuda_runtime.h>
#include <math.h>

#define BATCH 4096
#define FEAT  4096
#define WARPS_PER_BLOCK 9
#define THREADS (WARPS_PER_BLOCK * 32)          // 288
#define GRID ((BATCH + WARPS_PER_BLOCK - 1) / WARPS_PER_BLOCK)  // 456: all resident, 1 wave

__global__ __launch_bounds__(THREADS, 4)        // cap regs so 3-4 CTAs/SM fit
void fused_loss_kernel(const float* __restrict__ o1,
                       const float* __restrict__ o2,
                       const float* __restrict__ o3,
                       float* __restrict__ out) {
    const int tid  = threadIdx.x;
    const int lane = tid & 31;
    const int wid  = tid >> 5;

    __shared__ float s_block_sum;
    if (tid == 0) s_block_sum = 0.0f;
    __syncthreads();

    const int row = blockIdx.x * WARPS_PER_BLOCK + wid;
    if (row < BATCH) {
        const size_t base = (size_t)row * FEAT;
        const float4* __restrict__ a = reinterpret_cast<const float4*>(o1 + base);
        const float4* __restrict__ b = reinterpret_cast<const float4*>(o2 + base);
        const float4* __restrict__ c = reinterpret_cast<const float4*>(o3 + base);

        float s13 = 0.0f;
        float s12 = 0.0f;

        // 1024 float4 per row / 32 lanes = 32 iterations; unroll 2 -> 6 loads
        // in flight per lane, no block barriers anywhere in the hot path.
#pragma unroll 2
        for (int it = 0; it < (FEAT / 4) / 32; ++it) {
            int i = lane + it * 32;
            float4 x = a[i];
            float4 y = b[i];
            float4 z = c[i];

            float d;
            d = x.x - z.x; s13 = fmaf(d, d, s13);
            d = x.y - z.y; s13 = fmaf(d, d, s13);
            d = x.z - z.z; s13 = fmaf(d, d, s13);
            d = x.w - z.w; s13 = fmaf(d, d, s13);

            d = x.x - y.x; s12 = fmaf(d, d, s12);
            d = x.y - y.y; s12 = fmaf(d, d, s12);
            d = x.z - y.z; s12 = fmaf(d, d, s12);
            d = x.w - y.w; s12 = fmaf(d, d, s12);
        }

        // Warp-local reduction only.
#pragma unroll
        for (int off = 16; off > 0; off >>= 1) {
            s13 += __shfl_down_sync(0xFFFFFFFFu, s13, off);
            s12 += __shfl_down_sync(0xFFFFFFFFu, s12, off);
        }

        if (lane == 0) {
            float compare = 2.0f - sqrtf(s13) + sqrtf(s12);
            atomicAdd(&s_block_sum, fmaxf(0.0f, compare));  // smem atomic, 9/block
        }
    }
    __syncthreads();

    if (tid == 0) {
        // Broadcast-sum over [B,B] == B * sum_b(hinged). One overlapped ATOMG
        // per block; out[] zeroed by cudaMemsetAsync in kernel_launch.
        atomicAdd(out, s_block_sum * (float)BATCH);
    }
}

extern "C" void kernel_launch(void* const* d_in, const int* in_sizes, int n_in,
                              void* d_out, int out_size) {
    const float* o1 = (const float*)d_in[0];
    const float* o2 = (const float*)d_in[1];
    const float* o3 = (const float*)d_in[2];
    float* out = (float*)d_out;

    cudaMemsetAsync(out, 0, sizeof(float));
    fused_loss_kernel<<<GRID, THREADS>>>(o1, o2, o3, out);
}